// round 5
// baseline (speedup 1.0000x reference)
#include <cuda_runtime.h>
#include <math.h>

#define N_NODES 100000
#define N_EDGES 3200000
#define N_GRAPHS 128

// ---------------- device scratch (no runtime allocation allowed) ----------------
__device__ int   g_is64;                  // input index dtype flag (shared: edges & batch)
__device__ int   g_srcv[N_EDGES];         // edge srcs as int32
__device__ int   g_dstv[N_EDGES];         // edge dsts as int32
__device__ int   g_batchv[N_NODES];       // batch as int32
__device__ int   g_cnt[N_NODES];          // in-degree counts
__device__ float g_dinv[N_NODES];         // rsqrt(deg+1)
__device__ int   g_rowptr[N_NODES + 1];
__device__ int   g_cursor[N_NODES];
__device__ int   g_csr_src[N_EDGES];
__device__ float g_csr_w[N_EDGES];
__device__ float g_agg[N_NODES * 64];     // aggregated features (stride 20 or 64)
__device__ float g_h[N_NODES * 64];       // hidden features
__device__ float g_h3[N_NODES * 128];     // layer-3 output
__device__ float g_sums[N_GRAPHS * 128];  // pooled sums
__device__ int   g_gcnt[N_GRAPHS];        // nodes per graph

// ---------------- dtype probe (edges only; batch shares provenance/dtype) -------
// If the buffer is int64, all of the first 256 int64 values are valid ids in
// [0, N_NODES). If it is int32 reinterpreted as int64, each read combines two
// random ids as lo + hi*2^32; some hi is nonzero within 256 samples with
// overwhelming probability -> out of range -> int32 detected. Deterministic.
__global__ void k_detect(const void* p) {
    if (threadIdx.x != 0 || blockIdx.x != 0) return;
    const long long* q = (const long long*)p;
    int ok64 = 1;
    for (int i = 0; i < 256; i++) {
        long long v = q[i];
        if (v < 0 || v >= (long long)N_NODES) { ok64 = 0; break; }
    }
    g_is64 = ok64;
}

// ---------------- zero ----------------
__global__ void k_zero() {
    int i = blockIdx.x * blockDim.x + threadIdx.x;
    if (i < N_NODES) g_cnt[i] = 0;
    if (i < N_GRAPHS * 128) g_sums[i] = 0.f;
    if (i < N_GRAPHS) g_gcnt[i] = 0;
}

// ---------------- convert edges + count in-degree (fused) ----------------
__global__ void k_cvt_deg(const void* p) {
    int e = blockIdx.x * blockDim.x + threadIdx.x;
    if (e >= N_EDGES) return;
    int s, d;
    if (g_is64) {
        const long long* q = (const long long*)p;
        s = (int)q[e];
        d = (int)q[N_EDGES + e];
    } else {
        const int* q = (const int*)p;
        s = q[e];
        d = q[N_EDGES + e];
    }
    g_srcv[e] = s;
    g_dstv[e] = d;
    atomicAdd(&g_cnt[d], 1);
}

// ---------------- convert batch + graph node counts (fused) ----------------
__global__ void k_cvt_batch(const void* p) {
    int i = blockIdx.x * blockDim.x + threadIdx.x;
    if (i >= N_NODES) return;
    int b;
    if (g_is64) {
        const long long* q = (const long long*)p;
        b = (int)q[i];
    } else {
        const int* q = (const int*)p;
        b = q[i];
    }
    g_batchv[i] = b;
    atomicAdd(&g_gcnt[b], 1);
}

__global__ void k_dinv() {
    int i = blockIdx.x * blockDim.x + threadIdx.x;
    if (i >= N_NODES) return;
    g_dinv[i] = rsqrtf((float)g_cnt[i] + 1.0f);
}

// ---------------- single-block exclusive scan -> rowptr & cursor ----------------
__global__ void k_scan() {
    __shared__ int sh[1024];
    __shared__ int s_carry;
    int tid = threadIdx.x;
    if (tid == 0) s_carry = 0;
    __syncthreads();
    for (int base = 0; base < N_NODES; base += 1024) {
        int i = base + tid;
        int v = (i < N_NODES) ? g_cnt[i] : 0;
        sh[tid] = v;
        __syncthreads();
        #pragma unroll
        for (int off = 1; off < 1024; off <<= 1) {
            int t = (tid >= off) ? sh[tid - off] : 0;
            __syncthreads();
            sh[tid] += t;
            __syncthreads();
        }
        int excl = sh[tid] - v;
        int carry = s_carry;
        if (i < N_NODES) {
            g_rowptr[i] = carry + excl;
            g_cursor[i] = carry + excl;
        }
        __syncthreads();
        if (tid == 0) s_carry = carry + sh[1023];
        __syncthreads();
    }
    if (tid == 0) g_rowptr[N_NODES] = s_carry;
}

// ---------------- CSR fill (src index + precomputed norm weight) ----------------
__global__ void k_fill() {
    int e = blockIdx.x * blockDim.x + threadIdx.x;
    if (e >= N_EDGES) return;
    int s = g_srcv[e];
    int d = g_dstv[e];
    int pos = atomicAdd(&g_cursor[d], 1);
    g_csr_src[pos] = s;
    g_csr_w[pos] = g_dinv[s] * g_dinv[d];
}

// ---------------- aggregation F=20 (input x), warp per node ----------------
__global__ __launch_bounds__(256) void k_agg20(const float* __restrict__ x) {
    int warp = (blockIdx.x * blockDim.x + threadIdx.x) >> 5;
    int lane = threadIdx.x & 31;
    if (warp >= N_NODES) return;
    int i = warp;
    int beg = g_rowptr[i], end = g_rowptr[i + 1];
    float acc = 0.f;
    int e = beg;
    for (; e + 2 <= end; e += 2) {
        int s0 = g_csr_src[e];
        int s1 = g_csr_src[e + 1];
        float w0 = g_csr_w[e];
        float w1 = g_csr_w[e + 1];
        float v0 = (lane < 20) ? __ldg(&x[s0 * 20 + lane]) : 0.f;
        float v1 = (lane < 20) ? __ldg(&x[s1 * 20 + lane]) : 0.f;
        acc = fmaf(w0, v0, acc);
        acc = fmaf(w1, v1, acc);
    }
    if (e < end) {
        int s = g_csr_src[e];
        float w = g_csr_w[e];
        float v = (lane < 20) ? __ldg(&x[s * 20 + lane]) : 0.f;
        acc = fmaf(w, v, acc);
    }
    if (lane < 20) {
        float di = g_dinv[i];
        acc = fmaf(di * di, x[i * 20 + lane], acc);
        g_agg[i * 20 + lane] = acc;
    }
}

// ---------------- aggregation F=64 (g_h -> g_agg), warp per node, float2/lane ----
__global__ __launch_bounds__(256) void k_agg64() {
    int warp = (blockIdx.x * blockDim.x + threadIdx.x) >> 5;
    int lane = threadIdx.x & 31;
    if (warp >= N_NODES) return;
    int i = warp;
    const float2* in2 = (const float2*)g_h;
    int beg = g_rowptr[i], end = g_rowptr[i + 1];
    float ax = 0.f, ay = 0.f;
    int e = beg;
    for (; e + 2 <= end; e += 2) {
        int s0 = g_csr_src[e];
        int s1 = g_csr_src[e + 1];
        float w0 = g_csr_w[e];
        float w1 = g_csr_w[e + 1];
        float2 v0 = __ldg(&in2[s0 * 32 + lane]);
        float2 v1 = __ldg(&in2[s1 * 32 + lane]);
        ax = fmaf(w0, v0.x, ax); ay = fmaf(w0, v0.y, ay);
        ax = fmaf(w1, v1.x, ax); ay = fmaf(w1, v1.y, ay);
    }
    if (e < end) {
        int s = g_csr_src[e];
        float w = g_csr_w[e];
        float2 v = __ldg(&in2[s * 32 + lane]);
        ax = fmaf(w, v.x, ax); ay = fmaf(w, v.y, ay);
    }
    float di = g_dinv[i];
    float dd = di * di;
    float2 xv = in2[i * 32 + lane];
    ax = fmaf(dd, xv.x, ax); ay = fmaf(dd, xv.y, ay);
    float2 o; o.x = ax; o.y = ay;
    ((float2*)g_agg)[i * 32 + lane] = o;
}

// ---------------- dense matmul device helper ----------------
// in: [N, FIN] row-major, W: [FIN, FOUT], b: [FOUT], out: [N, FOUT]
// NPT=8 nodes per tile, JPT outputs per thread, blockDim = 8*(FOUT/JPT) = 256
template <int FIN, int FOUT, int JPT, bool RELU>
__device__ __forceinline__ void mm_body(const float* __restrict__ in,
                                        const float* __restrict__ W,
                                        const float* __restrict__ b,
                                        float* __restrict__ out) {
    constexpr int NPT = 8;
    constexpr int JW = FOUT / JPT;  // 32
    __shared__ float Ws[FIN * FOUT];
    __shared__ float bs[FOUT];
    __shared__ float rows[NPT][FIN];
    for (int k = threadIdx.x; k < FIN * FOUT; k += blockDim.x) Ws[k] = W[k];
    for (int k = threadIdx.x; k < FOUT; k += blockDim.x) bs[k] = b[k];
    __syncthreads();
    int ntiles = (N_NODES + NPT - 1) / NPT;
    int nn = threadIdx.x / JW;
    int j0 = threadIdx.x % JW;
    for (int tile = blockIdx.x; tile < ntiles; tile += gridDim.x) {
        int n0 = tile * NPT;
        for (int k = threadIdx.x; k < NPT * FIN; k += blockDim.x) {
            int rn = k / FIN, rk = k % FIN;
            int node = n0 + rn;
            rows[rn][rk] = (node < N_NODES) ? in[node * FIN + rk] : 0.f;
        }
        __syncthreads();
        int node = n0 + nn;
        if (node < N_NODES) {
            float acc[JPT];
            #pragma unroll
            for (int m = 0; m < JPT; m++) acc[m] = bs[j0 + m * JW];
            #pragma unroll
            for (int k = 0; k < FIN; k++) {
                float r = rows[nn][k];
                #pragma unroll
                for (int m = 0; m < JPT; m++)
                    acc[m] = fmaf(r, Ws[k * FOUT + j0 + m * JW], acc[m]);
            }
            #pragma unroll
            for (int m = 0; m < JPT; m++) {
                float v = RELU ? fmaxf(acc[m], 0.f) : acc[m];
                out[node * FOUT + j0 + m * JW] = v;
            }
        }
        __syncthreads();
    }
}

__global__ __launch_bounds__(256) void k_mm1(const float* __restrict__ W,
                                             const float* __restrict__ b) {
    mm_body<20, 64, 2, true>(g_agg, W, b, g_h);
}
__global__ __launch_bounds__(256) void k_mm2(const float* __restrict__ W,
                                             const float* __restrict__ b) {
    mm_body<64, 64, 2, true>(g_agg, W, b, g_h);
}
__global__ __launch_bounds__(256) void k_mm3(const float* __restrict__ W,
                                             const float* __restrict__ b) {
    mm_body<64, 128, 4, false>(g_agg, W, b, g_h3);
}

// ---------------- pooling: batch is sorted -> register accumulate, flush on change
__global__ __launch_bounds__(128) void k_pool() {
    const int CHUNK = 256;
    int j = threadIdx.x;  // 0..127 feature
    int n0 = blockIdx.x * CHUNK;
    if (n0 >= N_NODES) return;
    int n1 = n0 + CHUNK;
    if (n1 > N_NODES) n1 = N_NODES;
    float acc = 0.f;
    int gcur = g_batchv[n0];
    for (int n = n0; n < n1; n++) {
        int g = g_batchv[n];
        if (g != gcur) {
            atomicAdd(&g_sums[gcur * 128 + j], acc);
            acc = 0.f;
            gcur = g;
        }
        acc += g_h3[n * 128 + j];
    }
    atomicAdd(&g_sums[gcur * 128 + j], acc);
}

// ---------------- final: pooled@Wl + bl -> log_softmax ----------------
__global__ void k_final(const float* __restrict__ Wl,
                        const float* __restrict__ bl,
                        float* __restrict__ out) {
    int g = blockIdx.x;
    int lane = threadIdx.x;  // 32 threads
    float inv = 1.0f / fmaxf((float)g_gcnt[g], 1.0f);
    float l = -INFINITY;
    if (lane < 14) {
        float acc = bl[lane];
        #pragma unroll 4
        for (int k = 0; k < 128; k++)
            acc = fmaf(g_sums[g * 128 + k] * inv, Wl[k * 14 + lane], acc);
        l = acc;
    }
    float m = l;
    #pragma unroll
    for (int off = 16; off; off >>= 1)
        m = fmaxf(m, __shfl_xor_sync(0xFFFFFFFFu, m, off));
    float ex = (lane < 14) ? expf(l - m) : 0.f;
    float s = ex;
    #pragma unroll
    for (int off = 16; off; off >>= 1)
        s += __shfl_xor_sync(0xFFFFFFFFu, s, off);
    if (lane < 14) out[g * 14 + lane] = l - m - logf(s);
}

// ---------------- launch ----------------
extern "C" void kernel_launch(void* const* d_in, const int* in_sizes, int n_in,
                              void* d_out, int out_size) {
    const float* x     = (const float*)d_in[0];
    const void*  ei    = d_in[1];
    const void*  batch = d_in[2];
    const float* W1 = (const float*)d_in[3];
    const float* b1 = (const float*)d_in[4];
    const float* W2 = (const float*)d_in[5];
    const float* b2 = (const float*)d_in[6];
    const float* W3 = (const float*)d_in[7];
    const float* b3 = (const float*)d_in[8];
    const float* Wl = (const float*)d_in[9];
    const float* bl = (const float*)d_in[10];
    float* out = (float*)d_out;

    const int TB = 256;
    int nblkN = (N_NODES + TB - 1) / TB;
    int nblkE = (N_EDGES + TB - 1) / TB;
    int nblkW = (N_NODES + 7) / 8;          // warp-per-node, 8 warps/block
    int mmGrid = 148 * 8;

    k_detect<<<1, 32>>>(ei);
    k_zero<<<nblkN, TB>>>();
    k_cvt_deg<<<nblkE, TB>>>(ei);
    k_cvt_batch<<<nblkN, TB>>>(batch);
    k_dinv<<<nblkN, TB>>>();
    k_scan<<<1, 1024>>>();
    k_fill<<<nblkE, TB>>>();

    k_agg20<<<nblkW, TB>>>(x);
    k_mm1<<<mmGrid, TB>>>(W1, b1);

    k_agg64<<<nblkW, TB>>>();
    k_mm2<<<mmGrid, TB>>>(W2, b2);

    k_agg64<<<nblkW, TB>>>();
    k_mm3<<<mmGrid, TB>>>(W3, b3);

    k_pool<<<(N_NODES + 255) / 256, 128>>>();
    k_final<<<N_GRAPHS, 32>>>(Wl, bl, out);
}

// round 6
// speedup vs baseline: 1.9655x; 1.9655x over previous
#include <cuda_runtime.h>
#include <math.h>

#define N_NODES 100000
#define N_EDGES 3200000
#define N_GRAPHS 128
#define SCAN_CHUNKS 98            // ceil(100000/1024)

// ---------------- device scratch ----------------
__device__ int   g_is64;                   // index dtype flag (edges & batch share provenance)
__device__ int   g_cnt[N_NODES];           // in-degree
__device__ float g_dinv[N_NODES];          // rsqrt(deg+1)
__device__ int   g_rowptr[N_NODES + 1];
__device__ int   g_cursor[N_NODES];
__device__ int2  g_edge[N_EDGES];          // (src, bitcast weight)
__device__ float g_agg[N_NODES * 64];
__device__ float g_h[N_NODES * 64];
__device__ float g_psum[N_GRAPHS * 64];    // pooled 64-dim sums
__device__ int   g_start[N_GRAPHS + 1];    // graph start offsets (batch sorted)
__device__ int   g_bsum[128];
__device__ int   g_boff[128];

// ---------------- helpers ----------------
__device__ __forceinline__ int ld_idx(const void* p, long long i) {
    if (g_is64) return (int)((const long long*)p)[i];
    return ((const int*)p)[i];
}

// ---------------- dtype probe (edges; random ids -> reliable) ----------------
__global__ void k_detect(const void* p) {
    if (threadIdx.x != 0 || blockIdx.x != 0) return;
    const long long* q = (const long long*)p;
    int ok64 = 1;
    for (int i = 0; i < 256; i++) {
        long long v = q[i];
        if (v < 0 || v >= (long long)N_NODES) { ok64 = 0; break; }
    }
    g_is64 = ok64;
}

__global__ void k_zero() {
    int i = blockIdx.x * blockDim.x + threadIdx.x;
    if (i < N_NODES) g_cnt[i] = 0;
    if (i < N_GRAPHS * 64) g_psum[i] = 0.f;
}

__global__ void k_deg(const void* p) {
    int e = blockIdx.x * blockDim.x + threadIdx.x;
    if (e >= N_EDGES) return;
    atomicAdd(&g_cnt[ld_idx(p, (long long)N_EDGES + e)], 1);
}

// ---------------- multi-block scan ----------------
__global__ __launch_bounds__(1024) void k_scan1() {
    int tid = threadIdx.x;
    int lane = tid & 31, wid = tid >> 5;
    int i = blockIdx.x * 1024 + tid;
    int v = (i < N_NODES) ? g_cnt[i] : 0;
    int x = v;
    #pragma unroll
    for (int off = 1; off < 32; off <<= 1) {
        int t = __shfl_up_sync(0xFFFFFFFFu, x, off);
        if (lane >= off) x += t;
    }
    __shared__ int ws[32];
    if (lane == 31) ws[wid] = x;
    __syncthreads();
    if (wid == 0) {
        int y = ws[lane];
        #pragma unroll
        for (int off = 1; off < 32; off <<= 1) {
            int t = __shfl_up_sync(0xFFFFFFFFu, y, off);
            if (lane >= off) y += t;
        }
        ws[lane] = y;
    }
    __syncthreads();
    int incl = x + (wid > 0 ? ws[wid - 1] : 0);
    if (i < N_NODES) g_rowptr[i] = incl - v;  // block-local exclusive
    if (tid == 1023) g_bsum[blockIdx.x] = incl;
}

__global__ void k_scan2() {
    __shared__ int sh[128];
    int t = threadIdx.x;
    int v = (t < SCAN_CHUNKS) ? g_bsum[t] : 0;
    sh[t] = v;
    __syncthreads();
    #pragma unroll
    for (int off = 1; off < 128; off <<= 1) {
        int u = (t >= off) ? sh[t - off] : 0;
        __syncthreads();
        sh[t] += u;
        __syncthreads();
    }
    if (t < SCAN_CHUNKS) g_boff[t] = sh[t] - v;
    if (t == 127) g_rowptr[N_NODES] = sh[127];
}

__global__ void k_scan3() {
    int i = blockIdx.x * blockDim.x + threadIdx.x;
    if (i >= N_NODES) return;
    int r = g_rowptr[i] + g_boff[i >> 10];
    g_rowptr[i] = r;
    g_cursor[i] = r;
    g_dinv[i] = rsqrtf((float)g_cnt[i] + 1.0f);
}

// ---------------- graph boundaries from sorted batch (no atomics) ----------------
__global__ void k_bound(const void* p) {
    int i = blockIdx.x * blockDim.x + threadIdx.x;
    if (i >= N_NODES) return;
    int b = ld_idx(p, i);
    int prev = (i == 0) ? -1 : ld_idx(p, i - 1);
    for (int g = prev + 1; g <= b; g++) g_start[g] = i;
    if (i == N_NODES - 1)
        for (int g = b + 1; g <= N_GRAPHS; g++) g_start[g] = N_NODES;
}

// ---------------- CSR fill: (src, weight) as one int2 store ----------------
__global__ void k_fill(const void* p) {
    int e = blockIdx.x * blockDim.x + threadIdx.x;
    if (e >= N_EDGES) return;
    int s = ld_idx(p, e);
    int d = ld_idx(p, (long long)N_EDGES + e);
    int pos = atomicAdd(&g_cursor[d], 1);
    g_edge[pos] = make_int2(s, __float_as_int(g_dinv[s] * g_dinv[d]));
}

// ---------------- aggregation F=20, warp per node ----------------
__global__ __launch_bounds__(256) void k_agg20(const float* __restrict__ x) {
    int i = (blockIdx.x * blockDim.x + threadIdx.x) >> 5;
    int lane = threadIdx.x & 31;
    if (i >= N_NODES) return;
    int beg = g_rowptr[i], end = g_rowptr[i + 1];
    float acc = 0.f;
    int e = beg;
    for (; e + 2 <= end; e += 2) {
        int2 e0 = g_edge[e];
        int2 e1 = g_edge[e + 1];
        float v0 = (lane < 20) ? __ldg(&x[e0.x * 20 + lane]) : 0.f;
        float v1 = (lane < 20) ? __ldg(&x[e1.x * 20 + lane]) : 0.f;
        acc = fmaf(__int_as_float(e0.y), v0, acc);
        acc = fmaf(__int_as_float(e1.y), v1, acc);
    }
    if (e < end) {
        int2 e0 = g_edge[e];
        float v = (lane < 20) ? __ldg(&x[e0.x * 20 + lane]) : 0.f;
        acc = fmaf(__int_as_float(e0.y), v, acc);
    }
    if (lane < 20) {
        float di = g_dinv[i];
        acc = fmaf(di * di, x[i * 20 + lane], acc);
        g_agg[i * 20 + lane] = acc;
    }
}

// ---------------- aggregation F=64, warp per node, float2/lane ----------------
__global__ __launch_bounds__(256) void k_agg64() {
    int i = (blockIdx.x * blockDim.x + threadIdx.x) >> 5;
    int lane = threadIdx.x & 31;
    if (i >= N_NODES) return;
    const float2* in2 = (const float2*)g_h;
    int beg = g_rowptr[i], end = g_rowptr[i + 1];
    float ax = 0.f, ay = 0.f;
    int e = beg;
    for (; e + 2 <= end; e += 2) {
        int2 e0 = g_edge[e];
        int2 e1 = g_edge[e + 1];
        float2 v0 = __ldg(&in2[e0.x * 32 + lane]);
        float2 v1 = __ldg(&in2[e1.x * 32 + lane]);
        float w0 = __int_as_float(e0.y), w1 = __int_as_float(e1.y);
        ax = fmaf(w0, v0.x, ax); ay = fmaf(w0, v0.y, ay);
        ax = fmaf(w1, v1.x, ax); ay = fmaf(w1, v1.y, ay);
    }
    if (e < end) {
        int2 e0 = g_edge[e];
        float2 v = __ldg(&in2[e0.x * 32 + lane]);
        float w = __int_as_float(e0.y);
        ax = fmaf(w, v.x, ax); ay = fmaf(w, v.y, ay);
    }
    float di = g_dinv[i];
    float dd = di * di;
    float2 xv = in2[i * 32 + lane];
    ax = fmaf(dd, xv.x, ax); ay = fmaf(dd, xv.y, ay);
    float2 o; o.x = ax; o.y = ay;
    ((float2*)g_agg)[i * 32 + lane] = o;
}

// ---------------- FMA-bound matmul: 64-node tile, 4x4 outer product ----------------
// in [N, FIN] -> out [N, 64] (FOUT fixed 64). Per k: 2x LDS.128 feed 16 FMA.
template <int FIN, bool RELU>
__device__ __forceinline__ void mm_body(const float* __restrict__ in,
                                        const float* __restrict__ W,
                                        const float* __restrict__ b,
                                        float* __restrict__ out) {
    constexpr int FOUT = 64;
    constexpr int NT = 64;
    __shared__ float Ws[FIN * FOUT];
    __shared__ float bs[FOUT];
    __shared__ float rT[FIN][NT + 4];   // transposed rows, padded
    for (int k = threadIdx.x; k < FIN * FOUT; k += 256) Ws[k] = W[k];
    if (threadIdx.x < FOUT) bs[threadIdx.x] = b[threadIdx.x];
    int cg = threadIdx.x & 15;          // col group
    int ng = threadIdx.x >> 4;          // node group
    int c0 = cg * 4, nb = ng * 4;
    const int ntiles = (N_NODES + NT - 1) / NT;
    for (int tile = blockIdx.x; tile < ntiles; tile += gridDim.x) {
        int n0 = tile * NT;
        for (int idx = threadIdx.x; idx < NT * FIN; idx += 256) {
            int n = idx / FIN, k = idx - n * FIN;
            int node = n0 + n;
            rT[k][n] = (node < N_NODES) ? in[node * FIN + k] : 0.f;
        }
        __syncthreads();
        float a0x = bs[c0], a0y = bs[c0+1], a0z = bs[c0+2], a0w = bs[c0+3];
        float a1x = a0x, a1y = a0y, a1z = a0z, a1w = a0w;
        float a2x = a0x, a2y = a0y, a2z = a0z, a2w = a0w;
        float a3x = a0x, a3y = a0y, a3z = a0z, a3w = a0w;
        #pragma unroll 4
        for (int k = 0; k < FIN; k++) {
            float4 rv = *(const float4*)&rT[k][nb];
            float4 wv = *(const float4*)&Ws[k * FOUT + c0];
            a0x = fmaf(rv.x, wv.x, a0x); a0y = fmaf(rv.x, wv.y, a0y);
            a0z = fmaf(rv.x, wv.z, a0z); a0w = fmaf(rv.x, wv.w, a0w);
            a1x = fmaf(rv.y, wv.x, a1x); a1y = fmaf(rv.y, wv.y, a1y);
            a1z = fmaf(rv.y, wv.z, a1z); a1w = fmaf(rv.y, wv.w, a1w);
            a2x = fmaf(rv.z, wv.x, a2x); a2y = fmaf(rv.z, wv.y, a2y);
            a2z = fmaf(rv.z, wv.z, a2z); a2w = fmaf(rv.z, wv.w, a2w);
            a3x = fmaf(rv.w, wv.x, a3x); a3y = fmaf(rv.w, wv.y, a3y);
            a3z = fmaf(rv.w, wv.z, a3z); a3w = fmaf(rv.w, wv.w, a3w);
        }
        #define MM_STORE(NI, AX, AY, AZ, AW)                                  \
        {                                                                     \
            int node = n0 + nb + NI;                                          \
            if (node < N_NODES) {                                             \
                float4 o;                                                     \
                o.x = RELU ? fmaxf(AX, 0.f) : AX;                             \
                o.y = RELU ? fmaxf(AY, 0.f) : AY;                             \
                o.z = RELU ? fmaxf(AZ, 0.f) : AZ;                             \
                o.w = RELU ? fmaxf(AW, 0.f) : AW;                             \
                *(float4*)&out[node * FOUT + c0] = o;                         \
            }                                                                 \
        }
        MM_STORE(0, a0x, a0y, a0z, a0w)
        MM_STORE(1, a1x, a1y, a1z, a1w)
        MM_STORE(2, a2x, a2y, a2z, a2w)
        MM_STORE(3, a3x, a3y, a3z, a3w)
        #undef MM_STORE
        __syncthreads();
    }
}

__global__ __launch_bounds__(256) void k_mm1(const float* __restrict__ W,
                                             const float* __restrict__ b) {
    mm_body<20, true>(g_agg, W, b, g_h);
}
__global__ __launch_bounds__(256) void k_mm2(const float* __restrict__ W,
                                             const float* __restrict__ b) {
    mm_body<64, true>(g_agg, W, b, g_h);
}

// ---------------- pooling of 64-dim aggregated features (sorted batch) ----------
__global__ __launch_bounds__(64) void k_pool64(const void* batch) {
    const int CHUNK = 128;
    int j = threadIdx.x;
    int n0 = blockIdx.x * CHUNK;
    if (n0 >= N_NODES) return;
    int n1 = n0 + CHUNK; if (n1 > N_NODES) n1 = N_NODES;
    float acc = 0.f;
    int gcur = ld_idx(batch, n0);
    for (int n = n0; n < n1; n++) {
        int g = ld_idx(batch, n);
        if (g != gcur) {
            atomicAdd(&g_psum[gcur * 64 + j], acc);
            acc = 0.f;
            gcur = g;
        }
        acc += g_agg[n * 64 + j];
    }
    atomicAdd(&g_psum[gcur * 64 + j], acc);
}

// ---------------- final: (mean @ W3 + b3) @ Wl + bl -> log_softmax ----------------
__global__ __launch_bounds__(128) void k_final(const float* __restrict__ W3,
                                               const float* __restrict__ b3,
                                               const float* __restrict__ Wl,
                                               const float* __restrict__ bl,
                                               float* __restrict__ out) {
    int g = blockIdx.x;
    int j = threadIdx.x;  // 0..127
    __shared__ float sp[64];
    __shared__ float sf[128];
    int st = g_start[g], en = g_start[g + 1];
    float inv = 1.0f / fmaxf((float)(en - st), 1.0f);
    if (j < 64) sp[j] = g_psum[g * 64 + j] * inv;
    __syncthreads();
    float f = b3[j];
    #pragma unroll 8
    for (int k = 0; k < 64; k++)
        f = fmaf(sp[k], W3[k * 128 + j], f);
    sf[j] = f;
    __syncthreads();
    if (j < 32) {
        float l = -INFINITY;
        if (j < 14) {
            float acc = bl[j];
            #pragma unroll 8
            for (int k = 0; k < 128; k++)
                acc = fmaf(sf[k], Wl[k * 14 + j], acc);
            l = acc;
        }
        float m = l;
        #pragma unroll
        for (int off = 16; off; off >>= 1)
            m = fmaxf(m, __shfl_xor_sync(0xFFFFFFFFu, m, off));
        float ex = (j < 14) ? expf(l - m) : 0.f;
        float s = ex;
        #pragma unroll
        for (int off = 16; off; off >>= 1)
            s += __shfl_xor_sync(0xFFFFFFFFu, s, off);
        if (j < 14) out[g * 14 + j] = l - m - logf(s);
    }
}

// ---------------- launch ----------------
extern "C" void kernel_launch(void* const* d_in, const int* in_sizes, int n_in,
                              void* d_out, int out_size) {
    const float* x     = (const float*)d_in[0];
    const void*  ei    = d_in[1];
    const void*  batch = d_in[2];
    const float* W1 = (const float*)d_in[3];
    const float* b1 = (const float*)d_in[4];
    const float* W2 = (const float*)d_in[5];
    const float* b2 = (const float*)d_in[6];
    const float* W3 = (const float*)d_in[7];
    const float* b3 = (const float*)d_in[8];
    const float* Wl = (const float*)d_in[9];
    const float* bl = (const float*)d_in[10];
    float* out = (float*)d_out;

    const int TB = 256;
    int nblkN = (N_NODES + TB - 1) / TB;
    int nblkE = (N_EDGES + TB - 1) / TB;
    int nblkW = (N_NODES + 7) / 8;       // warp-per-node, 8 warps/block
    int mmGrid = 592;

    k_detect<<<1, 32>>>(ei);
    k_zero<<<nblkN, TB>>>();
    k_deg<<<nblkE, TB>>>(ei);
    k_scan1<<<SCAN_CHUNKS, 1024>>>();
    k_scan2<<<1, 128>>>();
    k_scan3<<<nblkN, TB>>>();
    k_bound<<<nblkN, TB>>>(batch);
    k_fill<<<nblkE, TB>>>(ei);

    k_agg20<<<nblkW, TB>>>(x);
    k_mm1<<<mmGrid, TB>>>(W1, b1);

    k_agg64<<<nblkW, TB>>>();
    k_mm2<<<mmGrid, TB>>>(W2, b2);

    k_agg64<<<nblkW, TB>>>();
    k_pool64<<<(N_NODES + 127) / 128, 64>>>(batch);
    k_final<<<N_GRAPHS, 128>>>(W3, b3, Wl, bl, out);
}

// round 7
// speedup vs baseline: 2.2645x; 1.1521x over previous
#include <cuda_runtime.h>
#include <cuda_fp16.h>
#include <math.h>

#define N_NODES 100000
#define N_EDGES 3200000
#define N_GRAPHS 128
#define SCAN_CHUNKS 98            // ceil(100000/1024)

// ---------------- device scratch ----------------
__device__ int   g_is64;
__device__ int   g_cnt[N_NODES];
__device__ float g_dinv[N_NODES];
__device__ int   g_rowptr[N_NODES + 1];
__device__ int   g_cursor[N_NODES];
__device__ int2  g_edge[N_EDGES];           // (src, bitcast weight)
__device__ float g_agg[N_NODES * 64];       // fp32 aggregation output
__device__ __half2 g_h16[N_NODES * 32];     // fp16 hidden features [N,64]
__device__ __half2 g_x16[N_NODES * 16];     // fp16 padded input    [N,32]
__device__ float g_psum[N_GRAPHS * 64];
__device__ int   g_start[N_GRAPHS + 1];
__device__ int   g_bsum[128];
__device__ int   g_boff[128];

// ---------------- helpers ----------------
__device__ __forceinline__ int ld_idx(const void* p, long long i) {
    if (g_is64) return (int)((const long long*)p)[i];
    return ((const int*)p)[i];
}

// ---------------- dtype probe ----------------
__global__ void k_detect(const void* p) {
    if (threadIdx.x != 0 || blockIdx.x != 0) return;
    const long long* q = (const long long*)p;
    int ok64 = 1;
    for (int i = 0; i < 256; i++) {
        long long v = q[i];
        if (v < 0 || v >= (long long)N_NODES) { ok64 = 0; break; }
    }
    g_is64 = ok64;
}

__global__ void k_zero() {
    int i = blockIdx.x * blockDim.x + threadIdx.x;
    if (i < N_NODES) g_cnt[i] = 0;
    if (i < N_GRAPHS * 64) g_psum[i] = 0.f;
}

__global__ void k_deg(const void* p) {
    int e = blockIdx.x * blockDim.x + threadIdx.x;
    if (e >= N_EDGES) return;
    atomicAdd(&g_cnt[ld_idx(p, (long long)N_EDGES + e)], 1);
}

// ---------------- x -> padded fp16 [N, 32] ----------------
__global__ void k_cvtx(const float* __restrict__ x) {
    int i = blockIdx.x * blockDim.x + threadIdx.x;
    if (i >= N_NODES * 16) return;
    int n = i >> 4, j = i & 15;
    int f = 2 * j;
    float a = (f < 20) ? x[n * 20 + f] : 0.f;
    float b = (f + 1 < 20) ? x[n * 20 + f + 1] : 0.f;
    g_x16[i] = __floats2half2_rn(a, b);
}

// ---------------- multi-block scan ----------------
__global__ __launch_bounds__(1024) void k_scan1() {
    int tid = threadIdx.x;
    int lane = tid & 31, wid = tid >> 5;
    int i = blockIdx.x * 1024 + tid;
    int v = (i < N_NODES) ? g_cnt[i] : 0;
    int x = v;
    #pragma unroll
    for (int off = 1; off < 32; off <<= 1) {
        int t = __shfl_up_sync(0xFFFFFFFFu, x, off);
        if (lane >= off) x += t;
    }
    __shared__ int ws[32];
    if (lane == 31) ws[wid] = x;
    __syncthreads();
    if (wid == 0) {
        int y = ws[lane];
        #pragma unroll
        for (int off = 1; off < 32; off <<= 1) {
            int t = __shfl_up_sync(0xFFFFFFFFu, y, off);
            if (lane >= off) y += t;
        }
        ws[lane] = y;
    }
    __syncthreads();
    int incl = x + (wid > 0 ? ws[wid - 1] : 0);
    if (i < N_NODES) g_rowptr[i] = incl - v;
    if (tid == 1023) g_bsum[blockIdx.x] = incl;
}

__global__ void k_scan2() {
    __shared__ int sh[128];
    int t = threadIdx.x;
    int v = (t < SCAN_CHUNKS) ? g_bsum[t] : 0;
    sh[t] = v;
    __syncthreads();
    #pragma unroll
    for (int off = 1; off < 128; off <<= 1) {
        int u = (t >= off) ? sh[t - off] : 0;
        __syncthreads();
        sh[t] += u;
        __syncthreads();
    }
    if (t < SCAN_CHUNKS) g_boff[t] = sh[t] - v;
    if (t == 127) g_rowptr[N_NODES] = sh[127];
}

__global__ void k_scan3() {
    int i = blockIdx.x * blockDim.x + threadIdx.x;
    if (i >= N_NODES) return;
    int r = g_rowptr[i] + g_boff[i >> 10];
    g_rowptr[i] = r;
    g_cursor[i] = r;
    g_dinv[i] = rsqrtf((float)g_cnt[i] + 1.0f);
}

// ---------------- graph boundaries (batch sorted, no atomics) ----------------
__global__ void k_bound(const void* p) {
    int i = blockIdx.x * blockDim.x + threadIdx.x;
    if (i >= N_NODES) return;
    int b = ld_idx(p, i);
    int prev = (i == 0) ? -1 : ld_idx(p, i - 1);
    for (int g = prev + 1; g <= b; g++) g_start[g] = i;
    if (i == N_NODES - 1)
        for (int g = b + 1; g <= N_GRAPHS; g++) g_start[g] = N_NODES;
}

// ---------------- CSR fill ----------------
__global__ void k_fill(const void* p) {
    int e = blockIdx.x * blockDim.x + threadIdx.x;
    if (e >= N_EDGES) return;
    int s = ld_idx(p, e);
    int d = ld_idx(p, (long long)N_EDGES + e);
    int pos = atomicAdd(&g_cursor[d], 1);
    g_edge[pos] = make_int2(s, __float_as_int(g_dinv[s] * g_dinv[d]));
}

// ---------------- aggregation F=20: 2 edges/warp-iter on fp16 padded x --------
// lanes 0-15 process even edge offsets, lanes 16-31 odd; lane half-index lj
// owns features 2lj, 2lj+1. Combine groups via shfl_xor(16) at the end.
__global__ __launch_bounds__(256) void k_agg20(const float* __restrict__ x) {
    int i = (blockIdx.x * blockDim.x + threadIdx.x) >> 5;
    int lane = threadIdx.x & 31;
    if (i >= N_NODES) return;
    int grp = lane >> 4;       // 0 or 1
    int lj = lane & 15;        // half2 index 0..15
    int beg = g_rowptr[i], end = g_rowptr[i + 1];
    float ax = 0.f, ay = 0.f;
    for (int e = beg + grp; e < end; e += 2) {
        int2 ed = g_edge[e];
        float w = __int_as_float(ed.y);
        float2 v = __half22float2(__ldg(&g_x16[ed.x * 16 + lj]));
        ax = fmaf(w, v.x, ax);
        ay = fmaf(w, v.y, ay);
    }
    ax += __shfl_xor_sync(0xFFFFFFFFu, ax, 16);
    ay += __shfl_xor_sync(0xFFFFFFFFu, ay, 16);
    if (lane < 10) {           // features 0..19
        float di = g_dinv[i];
        float dd = di * di;
        int f = 2 * lane;
        float2 o;
        o.x = fmaf(dd, x[i * 20 + f], ax);
        o.y = fmaf(dd, x[i * 20 + f + 1], ay);
        *(float2*)&g_agg[i * 20 + f] = o;
    }
}

// ---------------- aggregation F=64 on fp16 h, warp per node ----------------
__global__ __launch_bounds__(256) void k_agg64() {
    int i = (blockIdx.x * blockDim.x + threadIdx.x) >> 5;
    int lane = threadIdx.x & 31;
    if (i >= N_NODES) return;
    int beg = g_rowptr[i], end = g_rowptr[i + 1];
    float ax = 0.f, ay = 0.f;
    int e = beg;
    for (; e + 2 <= end; e += 2) {
        int2 e0 = g_edge[e];
        int2 e1 = g_edge[e + 1];
        float2 v0 = __half22float2(__ldg(&g_h16[e0.x * 32 + lane]));
        float2 v1 = __half22float2(__ldg(&g_h16[e1.x * 32 + lane]));
        float w0 = __int_as_float(e0.y), w1 = __int_as_float(e1.y);
        ax = fmaf(w0, v0.x, ax); ay = fmaf(w0, v0.y, ay);
        ax = fmaf(w1, v1.x, ax); ay = fmaf(w1, v1.y, ay);
    }
    if (e < end) {
        int2 e0 = g_edge[e];
        float2 v = __half22float2(__ldg(&g_h16[e0.x * 32 + lane]));
        float w = __int_as_float(e0.y);
        ax = fmaf(w, v.x, ax); ay = fmaf(w, v.y, ay);
    }
    float di = g_dinv[i];
    float dd = di * di;
    float2 xv = __half22float2(g_h16[i * 32 + lane]);
    ax = fmaf(dd, xv.x, ax); ay = fmaf(dd, xv.y, ay);
    float2 o; o.x = ax; o.y = ay;
    ((float2*)g_agg)[i * 32 + lane] = o;
}

// ---------------- FMA-bound matmul: 64-node tile, 4x4 outer product -----------
// in [N, FIN] fp32 -> out [N, 64] fp16 (ReLU applied). Per k: 2x LDS.128 -> 16 FMA.
template <int FIN>
__device__ __forceinline__ void mm_body_h(const float* __restrict__ in,
                                          const float* __restrict__ W,
                                          const float* __restrict__ b) {
    constexpr int FOUT = 64;
    constexpr int NT = 64;
    __shared__ float Ws[FIN * FOUT];
    __shared__ float bs[FOUT];
    __shared__ float rT[FIN][NT + 4];
    for (int k = threadIdx.x; k < FIN * FOUT; k += 256) Ws[k] = W[k];
    if (threadIdx.x < FOUT) bs[threadIdx.x] = b[threadIdx.x];
    int cg = threadIdx.x & 15;
    int ng = threadIdx.x >> 4;
    int c0 = cg * 4, nb = ng * 4;
    const int ntiles = (N_NODES + NT - 1) / NT;
    for (int tile = blockIdx.x; tile < ntiles; tile += gridDim.x) {
        int n0 = tile * NT;
        for (int idx = threadIdx.x; idx < NT * FIN; idx += 256) {
            int n = idx / FIN, k = idx - n * FIN;
            int node = n0 + n;
            rT[k][n] = (node < N_NODES) ? in[node * FIN + k] : 0.f;
        }
        __syncthreads();
        float a0x = bs[c0], a0y = bs[c0+1], a0z = bs[c0+2], a0w = bs[c0+3];
        float a1x = a0x, a1y = a0y, a1z = a0z, a1w = a0w;
        float a2x = a0x, a2y = a0y, a2z = a0z, a2w = a0w;
        float a3x = a0x, a3y = a0y, a3z = a0z, a3w = a0w;
        #pragma unroll 4
        for (int k = 0; k < FIN; k++) {
            float4 rv = *(const float4*)&rT[k][nb];
            float4 wv = *(const float4*)&Ws[k * FOUT + c0];
            a0x = fmaf(rv.x, wv.x, a0x); a0y = fmaf(rv.x, wv.y, a0y);
            a0z = fmaf(rv.x, wv.z, a0z); a0w = fmaf(rv.x, wv.w, a0w);
            a1x = fmaf(rv.y, wv.x, a1x); a1y = fmaf(rv.y, wv.y, a1y);
            a1z = fmaf(rv.y, wv.z, a1z); a1w = fmaf(rv.y, wv.w, a1w);
            a2x = fmaf(rv.z, wv.x, a2x); a2y = fmaf(rv.z, wv.y, a2y);
            a2z = fmaf(rv.z, wv.z, a2z); a2w = fmaf(rv.z, wv.w, a2w);
            a3x = fmaf(rv.w, wv.x, a3x); a3y = fmaf(rv.w, wv.y, a3y);
            a3z = fmaf(rv.w, wv.z, a3z); a3w = fmaf(rv.w, wv.w, a3w);
        }
        #define MM_STORE_H(NI, AX, AY, AZ, AW)                                \
        {                                                                     \
            int node = n0 + nb + NI;                                          \
            if (node < N_NODES) {                                             \
                __half2 h01 = __floats2half2_rn(fmaxf(AX, 0.f), fmaxf(AY, 0.f)); \
                __half2 h23 = __floats2half2_rn(fmaxf(AZ, 0.f), fmaxf(AW, 0.f)); \
                uint2 u;                                                      \
                u.x = *reinterpret_cast<unsigned*>(&h01);                     \
                u.y = *reinterpret_cast<unsigned*>(&h23);                     \
                *(uint2*)&g_h16[node * 32 + (c0 >> 1)] = u;                   \
            }                                                                 \
        }
        MM_STORE_H(0, a0x, a0y, a0z, a0w)
        MM_STORE_H(1, a1x, a1y, a1z, a1w)
        MM_STORE_H(2, a2x, a2y, a2z, a2w)
        MM_STORE_H(3, a3x, a3y, a3z, a3w)
        #undef MM_STORE_H
        __syncthreads();
    }
}

__global__ __launch_bounds__(256) void k_mm1(const float* __restrict__ W,
                                             const float* __restrict__ b) {
    mm_body_h<20>(g_agg, W, b);
}
__global__ __launch_bounds__(256) void k_mm2(const float* __restrict__ W,
                                             const float* __restrict__ b) {
    mm_body_h<64>(g_agg, W, b);
}

// ---------------- pooling of 64-dim aggregated features (sorted batch) ---------
__global__ __launch_bounds__(64) void k_pool64(const void* batch) {
    const int CHUNK = 128;
    int j = threadIdx.x;
    int n0 = blockIdx.x * CHUNK;
    if (n0 >= N_NODES) return;
    int n1 = n0 + CHUNK; if (n1 > N_NODES) n1 = N_NODES;
    float acc = 0.f;
    int gcur = ld_idx(batch, n0);
    for (int n = n0; n < n1; n++) {
        int g = ld_idx(batch, n);
        if (g != gcur) {
            atomicAdd(&g_psum[gcur * 64 + j], acc);
            acc = 0.f;
            gcur = g;
        }
        acc += g_agg[n * 64 + j];
    }
    atomicAdd(&g_psum[gcur * 64 + j], acc);
}

// ---------------- final: (mean @ W3 + b3) @ Wl + bl -> log_softmax -------------
__global__ __launch_bounds__(128) void k_final(const float* __restrict__ W3,
                                               const float* __restrict__ b3,
                                               const float* __restrict__ Wl,
                                               const float* __restrict__ bl,
                                               float* __restrict__ out) {
    int g = blockIdx.x;
    int j = threadIdx.x;
    __shared__ float sp[64];
    __shared__ float sf[128];
    int st = g_start[g], en = g_start[g + 1];
    float inv = 1.0f / fmaxf((float)(en - st), 1.0f);
    if (j < 64) sp[j] = g_psum[g * 64 + j] * inv;
    __syncthreads();
    float f = b3[j];
    #pragma unroll 8
    for (int k = 0; k < 64; k++)
        f = fmaf(sp[k], W3[k * 128 + j], f);
    sf[j] = f;
    __syncthreads();
    if (j < 32) {
        float l = -INFINITY;
        if (j < 14) {
            float acc = bl[j];
            #pragma unroll 8
            for (int k = 0; k < 128; k++)
                acc = fmaf(sf[k], Wl[k * 14 + j], acc);
            l = acc;
        }
        float m = l;
        #pragma unroll
        for (int off = 16; off; off >>= 1)
            m = fmaxf(m, __shfl_xor_sync(0xFFFFFFFFu, m, off));
        float ex = (j < 14) ? expf(l - m) : 0.f;
        float s = ex;
        #pragma unroll
        for (int off = 16; off; off >>= 1)
            s += __shfl_xor_sync(0xFFFFFFFFu, s, off);
        if (j < 14) out[g * 14 + j] = l - m - logf(s);
    }
}

// ---------------- launch ----------------
extern "C" void kernel_launch(void* const* d_in, const int* in_sizes, int n_in,
                              void* d_out, int out_size) {
    const float* x     = (const float*)d_in[0];
    const void*  ei    = d_in[1];
    const void*  batch = d_in[2];
    const float* W1 = (const float*)d_in[3];
    const float* b1 = (const float*)d_in[4];
    const float* W2 = (const float*)d_in[5];
    const float* b2 = (const float*)d_in[6];
    const float* W3 = (const float*)d_in[7];
    const float* b3 = (const float*)d_in[8];
    const float* Wl = (const float*)d_in[9];
    const float* bl = (const float*)d_in[10];
    float* out = (float*)d_out;

    const int TB = 256;
    int nblkN = (N_NODES + TB - 1) / TB;
    int nblkE = (N_EDGES + TB - 1) / TB;
    int nblkW = (N_NODES + 7) / 8;
    int mmGrid = 592;

    k_detect<<<1, 32>>>(ei);
    k_zero<<<nblkN, TB>>>();
    k_deg<<<nblkE, TB>>>(ei);
    k_cvtx<<<(N_NODES * 16 + TB - 1) / TB, TB>>>(x);
    k_scan1<<<SCAN_CHUNKS, 1024>>>();
    k_scan2<<<1, 128>>>();
    k_scan3<<<nblkN, TB>>>();
    k_bound<<<nblkN, TB>>>(batch);
    k_fill<<<nblkE, TB>>>(ei);

    k_agg20<<<nblkW, TB>>>(x);
    k_mm1<<<mmGrid, TB>>>(W1, b1);

    k_agg64<<<nblkW, TB>>>();
    k_mm2<<<mmGrid, TB>>>(W2, b2);

    k_agg64<<<nblkW, TB>>>();
    k_pool64<<<(N_NODES + 127) / 128, 64>>>(batch);
    k_final<<<N_GRAPHS, 128>>>(W3, b3, Wl, bl, out);
}

// round 8
// speedup vs baseline: 2.3903x; 1.0556x over previous
#include <cuda_runtime.h>
#include <cuda_fp16.h>
#include <math.h>

#define N_NODES 100000
#define N_EDGES 3200000
#define N_GRAPHS 128
#define SCAN_CHUNKS 98            // ceil(100000/1024)

// ---------------- device scratch ----------------
__device__ int   g_is64;
__device__ int   g_cnt[N_NODES];
__device__ float g_dinv[N_NODES];
__device__ int   g_rowptr[N_NODES + 1];
__device__ int   g_cursor[N_NODES];
__device__ int2  g_edge[N_EDGES];           // (src, bitcast weight)
__device__ float g_agg[N_NODES * 64];       // fp32 aggregation output
__device__ __half2 g_h16[N_NODES * 32];     // fp16 hidden features [N,64]
__device__ __half2 g_x16[N_NODES * 16];     // fp16 padded input    [N,32]
__device__ float g_psum[N_GRAPHS * 64];
__device__ int   g_start[N_GRAPHS + 1];
__device__ int   g_bsum[128];
__device__ int   g_boff[128];

// ---------------- helpers ----------------
__device__ __forceinline__ int ld_idx(const void* p, long long i) {
    if (g_is64) return (int)((const long long*)p)[i];
    return ((const int*)p)[i];
}

// ---------------- dtype probe ----------------
__global__ void k_detect(const void* p) {
    if (threadIdx.x != 0 || blockIdx.x != 0) return;
    const long long* q = (const long long*)p;
    int ok64 = 1;
    for (int i = 0; i < 256; i++) {
        long long v = q[i];
        if (v < 0 || v >= (long long)N_NODES) { ok64 = 0; break; }
    }
    g_is64 = ok64;
}

// ---------------- prep: zero counters + convert x to padded fp16 [N,32] -------
__global__ void k_prep(const float* __restrict__ x) {
    int i = blockIdx.x * blockDim.x + threadIdx.x;
    if (i < N_NODES) g_cnt[i] = 0;
    if (i < N_GRAPHS * 64) g_psum[i] = 0.f;
    if (i < N_NODES * 16) {
        int n = i >> 4, j = i & 15;
        int f = 2 * j;
        float a = (f < 20) ? x[n * 20 + f] : 0.f;
        float b = (f + 1 < 20) ? x[n * 20 + f + 1] : 0.f;
        g_x16[i] = __floats2half2_rn(a, b);
    }
}

// ---------------- graph boundaries (batch sorted, no atomics) ----------------
__global__ void k_bound(const void* p) {
    int i = blockIdx.x * blockDim.x + threadIdx.x;
    if (i >= N_NODES) return;
    int b = ld_idx(p, i);
    int prev = (i == 0) ? -1 : ld_idx(p, i - 1);
    for (int g = prev + 1; g <= b; g++) g_start[g] = i;
    if (i == N_NODES - 1)
        for (int g = b + 1; g <= N_GRAPHS; g++) g_start[g] = N_NODES;
}

// ---------------- degree count: 4 edges/thread, 16B loads ----------------
__global__ void k_deg(const void* p) {
    int t = blockIdx.x * blockDim.x + threadIdx.x;
    if (t >= N_EDGES / 4) return;
    int d0, d1, d2, d3;
    if (g_is64) {
        const longlong2* q = (const longlong2*)((const long long*)p + N_EDGES);
        longlong2 a = __ldg(&q[2 * t]);
        longlong2 b = __ldg(&q[2 * t + 1]);
        d0 = (int)a.x; d1 = (int)a.y; d2 = (int)b.x; d3 = (int)b.y;
    } else {
        const int4* q = (const int4*)((const int*)p + N_EDGES);
        int4 v = __ldg(&q[t]);
        d0 = v.x; d1 = v.y; d2 = v.z; d3 = v.w;
    }
    atomicAdd(&g_cnt[d0], 1);
    atomicAdd(&g_cnt[d1], 1);
    atomicAdd(&g_cnt[d2], 1);
    atomicAdd(&g_cnt[d3], 1);
}

// ---------------- multi-block scan ----------------
__global__ __launch_bounds__(1024) void k_scan1() {
    int tid = threadIdx.x;
    int lane = tid & 31, wid = tid >> 5;
    int i = blockIdx.x * 1024 + tid;
    int v = (i < N_NODES) ? g_cnt[i] : 0;
    int x = v;
    #pragma unroll
    for (int off = 1; off < 32; off <<= 1) {
        int t = __shfl_up_sync(0xFFFFFFFFu, x, off);
        if (lane >= off) x += t;
    }
    __shared__ int ws[32];
    if (lane == 31) ws[wid] = x;
    __syncthreads();
    if (wid == 0) {
        int y = ws[lane];
        #pragma unroll
        for (int off = 1; off < 32; off <<= 1) {
            int t = __shfl_up_sync(0xFFFFFFFFu, y, off);
            if (lane >= off) y += t;
        }
        ws[lane] = y;
    }
    __syncthreads();
    int incl = x + (wid > 0 ? ws[wid - 1] : 0);
    if (i < N_NODES) g_rowptr[i] = incl - v;
    if (tid == 1023) g_bsum[blockIdx.x] = incl;
}

__global__ void k_scan2() {
    __shared__ int sh[128];
    int t = threadIdx.x;
    int v = (t < SCAN_CHUNKS) ? g_bsum[t] : 0;
    sh[t] = v;
    __syncthreads();
    #pragma unroll
    for (int off = 1; off < 128; off <<= 1) {
        int u = (t >= off) ? sh[t - off] : 0;
        __syncthreads();
        sh[t] += u;
        __syncthreads();
    }
    if (t < SCAN_CHUNKS) g_boff[t] = sh[t] - v;
    if (t == 127) g_rowptr[N_NODES] = sh[127];
}

__global__ void k_scan3() {
    int i = blockIdx.x * blockDim.x + threadIdx.x;
    if (i >= N_NODES) return;
    int r = g_rowptr[i] + g_boff[i >> 10];
    g_rowptr[i] = r;
    g_cursor[i] = r;
    g_dinv[i] = rsqrtf((float)g_cnt[i] + 1.0f);
}

// ---------------- CSR fill: 2 edges/thread ----------------
__global__ void k_fill(const void* p) {
    int t = blockIdx.x * blockDim.x + threadIdx.x;
    if (t >= N_EDGES / 2) return;
    int s0, s1, d0, d1;
    if (g_is64) {
        const longlong2* qs = (const longlong2*)p;
        const longlong2* qd = (const longlong2*)((const long long*)p + N_EDGES);
        longlong2 sv = __ldg(&qs[t]);
        longlong2 dv = __ldg(&qd[t]);
        s0 = (int)sv.x; s1 = (int)sv.y;
        d0 = (int)dv.x; d1 = (int)dv.y;
    } else {
        const int2* qs = (const int2*)p;
        const int2* qd = (const int2*)((const int*)p + N_EDGES);
        int2 sv = __ldg(&qs[t]);
        int2 dv = __ldg(&qd[t]);
        s0 = sv.x; s1 = sv.y;
        d0 = dv.x; d1 = dv.y;
    }
    int p0 = atomicAdd(&g_cursor[d0], 1);
    g_edge[p0] = make_int2(s0, __float_as_int(g_dinv[s0] * g_dinv[d0]));
    int p1 = atomicAdd(&g_cursor[d1], 1);
    g_edge[p1] = make_int2(s1, __float_as_int(g_dinv[s1] * g_dinv[d1]));
}

// ---------------- aggregation F=20: 2 lane-groups x 2-deep unroll --------------
__global__ __launch_bounds__(256) void k_agg20(const float* __restrict__ x) {
    int i = (blockIdx.x * blockDim.x + threadIdx.x) >> 5;
    int lane = threadIdx.x & 31;
    int grp = lane >> 4;
    int lj = lane & 15;
    int beg = g_rowptr[i], end = g_rowptr[i + 1];
    float ax = 0.f, ay = 0.f;
    int e = beg + grp;
    for (; e + 2 < end; e += 4) {
        int2 e0 = g_edge[e];
        int2 e1 = g_edge[e + 2];
        float2 v0 = __half22float2(__ldg(&g_x16[e0.x * 16 + lj]));
        float2 v1 = __half22float2(__ldg(&g_x16[e1.x * 16 + lj]));
        float w0 = __int_as_float(e0.y), w1 = __int_as_float(e1.y);
        ax = fmaf(w0, v0.x, ax); ay = fmaf(w0, v0.y, ay);
        ax = fmaf(w1, v1.x, ax); ay = fmaf(w1, v1.y, ay);
    }
    if (e < end) {
        int2 e0 = g_edge[e];
        float2 v = __half22float2(__ldg(&g_x16[e0.x * 16 + lj]));
        float w = __int_as_float(e0.y);
        ax = fmaf(w, v.x, ax); ay = fmaf(w, v.y, ay);
    }
    ax += __shfl_xor_sync(0xFFFFFFFFu, ax, 16);
    ay += __shfl_xor_sync(0xFFFFFFFFu, ay, 16);
    if (lane < 10) {
        float di = g_dinv[i];
        float dd = di * di;
        int f = 2 * lane;
        float2 o;
        o.x = fmaf(dd, x[i * 20 + f], ax);
        o.y = fmaf(dd, x[i * 20 + f + 1], ay);
        *(float2*)&g_agg[i * 20 + f] = o;
    }
}

// ---------------- aggregation F=64, warp per node, 4-edge unroll ----------------
// POOL=false: write g_agg.  POOL=true: reduce into g_psum (batch sorted; blocks
// of 8 consecutive nodes are nearly always one graph -> SMEM reduce + 64 atomics).
template <bool POOL>
__device__ __forceinline__ void agg64_body(const void* batch) {
    __shared__ float sacc[64];
    __shared__ int sg;
    int i = (blockIdx.x * blockDim.x + threadIdx.x) >> 5;   // grid exact: no tail
    int lane = threadIdx.x & 31;
    if (POOL) {
        if (threadIdx.x < 64) sacc[threadIdx.x] = 0.f;
        if (threadIdx.x == 0) sg = ld_idx(batch, (blockIdx.x * blockDim.x) >> 5);
        __syncthreads();
    }
    int beg = g_rowptr[i], end = g_rowptr[i + 1];
    float ax = 0.f, ay = 0.f;
    int e = beg;
    for (; e + 4 <= end; e += 4) {
        int2 e0 = g_edge[e];
        int2 e1 = g_edge[e + 1];
        int2 e2 = g_edge[e + 2];
        int2 e3 = g_edge[e + 3];
        float2 v0 = __half22float2(__ldg(&g_h16[e0.x * 32 + lane]));
        float2 v1 = __half22float2(__ldg(&g_h16[e1.x * 32 + lane]));
        float2 v2 = __half22float2(__ldg(&g_h16[e2.x * 32 + lane]));
        float2 v3 = __half22float2(__ldg(&g_h16[e3.x * 32 + lane]));
        float w0 = __int_as_float(e0.y), w1 = __int_as_float(e1.y);
        float w2 = __int_as_float(e2.y), w3 = __int_as_float(e3.y);
        ax = fmaf(w0, v0.x, ax); ay = fmaf(w0, v0.y, ay);
        ax = fmaf(w1, v1.x, ax); ay = fmaf(w1, v1.y, ay);
        ax = fmaf(w2, v2.x, ax); ay = fmaf(w2, v2.y, ay);
        ax = fmaf(w3, v3.x, ax); ay = fmaf(w3, v3.y, ay);
    }
    for (; e < end; e++) {
        int2 e0 = g_edge[e];
        float2 v = __half22float2(__ldg(&g_h16[e0.x * 32 + lane]));
        float w = __int_as_float(e0.y);
        ax = fmaf(w, v.x, ax); ay = fmaf(w, v.y, ay);
    }
    float di = g_dinv[i];
    float dd = di * di;
    float2 xv = __half22float2(g_h16[i * 32 + lane]);
    ax = fmaf(dd, xv.x, ax); ay = fmaf(dd, xv.y, ay);
    if (!POOL) {
        float2 o; o.x = ax; o.y = ay;
        ((float2*)g_agg)[i * 32 + lane] = o;
    } else {
        int b = ld_idx(batch, i);
        int uniform = __syncthreads_and(b == sg);
        if (uniform) {
            atomicAdd(&sacc[2 * lane], ax);
            atomicAdd(&sacc[2 * lane + 1], ay);
            __syncthreads();
            if (threadIdx.x < 64)
                atomicAdd(&g_psum[sg * 64 + threadIdx.x], sacc[threadIdx.x]);
        } else {
            atomicAdd(&g_psum[b * 64 + 2 * lane], ax);
            atomicAdd(&g_psum[b * 64 + 2 * lane + 1], ay);
        }
    }
}

__global__ __launch_bounds__(256) void k_agg64() { agg64_body<false>(nullptr); }
__global__ __launch_bounds__(256) void k_agg64_pool(const void* batch) {
    agg64_body<true>(batch);
}

// ---------------- FMA-bound matmul: 64-node tile, 4x4 outer product -----------
template <int FIN>
__device__ __forceinline__ void mm_body_h(const float* __restrict__ in,
                                          const float* __restrict__ W,
                                          const float* __restrict__ b) {
    constexpr int FOUT = 64;
    constexpr int NT = 64;
    __shared__ float Ws[FIN * FOUT];
    __shared__ float bs[FOUT];
    __shared__ float rT[FIN][NT + 4];
    for (int k = threadIdx.x; k < FIN * FOUT; k += 256) Ws[k] = W[k];
    if (threadIdx.x < FOUT) bs[threadIdx.x] = b[threadIdx.x];
    int cg = threadIdx.x & 15;
    int ng = threadIdx.x >> 4;
    int c0 = cg * 4, nb = ng * 4;
    const int ntiles = (N_NODES + NT - 1) / NT;
    for (int tile = blockIdx.x; tile < ntiles; tile += gridDim.x) {
        int n0 = tile * NT;
        for (int idx = threadIdx.x; idx < NT * FIN; idx += 256) {
            int n = idx / FIN, k = idx - n * FIN;
            int node = n0 + n;
            rT[k][n] = (node < N_NODES) ? in[node * FIN + k] : 0.f;
        }
        __syncthreads();
        float a0x = bs[c0], a0y = bs[c0+1], a0z = bs[c0+2], a0w = bs[c0+3];
        float a1x = a0x, a1y = a0y, a1z = a0z, a1w = a0w;
        float a2x = a0x, a2y = a0y, a2z = a0z, a2w = a0w;
        float a3x = a0x, a3y = a0y, a3z = a0z, a3w = a0w;
        #pragma unroll 4
        for (int k = 0; k < FIN; k++) {
            float4 rv = *(const float4*)&rT[k][nb];
            float4 wv = *(const float4*)&Ws[k * FOUT + c0];
            a0x = fmaf(rv.x, wv.x, a0x); a0y = fmaf(rv.x, wv.y, a0y);
            a0z = fmaf(rv.x, wv.z, a0z); a0w = fmaf(rv.x, wv.w, a0w);
            a1x = fmaf(rv.y, wv.x, a1x); a1y = fmaf(rv.y, wv.y, a1y);
            a1z = fmaf(rv.y, wv.z, a1z); a1w = fmaf(rv.y, wv.w, a1w);
            a2x = fmaf(rv.z, wv.x, a2x); a2y = fmaf(rv.z, wv.y, a2y);
            a2z = fmaf(rv.z, wv.z, a2z); a2w = fmaf(rv.z, wv.w, a2w);
            a3x = fmaf(rv.w, wv.x, a3x); a3y = fmaf(rv.w, wv.y, a3y);
            a3z = fmaf(rv.w, wv.z, a3z); a3w = fmaf(rv.w, wv.w, a3w);
        }
        #define MM_STORE_H(NI, AX, AY, AZ, AW)                                \
        {                                                                     \
            int node = n0 + nb + NI;                                          \
            if (node < N_NODES) {                                             \
                __half2 h01 = __floats2half2_rn(fmaxf(AX, 0.f), fmaxf(AY, 0.f)); \
                __half2 h23 = __floats2half2_rn(fmaxf(AZ, 0.f), fmaxf(AW, 0.f)); \
                uint2 u;                                                      \
                u.x = *reinterpret_cast<unsigned*>(&h01);                     \
                u.y = *reinterpret_cast<unsigned*>(&h23);                     \
                *(uint2*)&g_h16[node * 32 + (c0 >> 1)] = u;                   \
            }                                                                 \
        }
        MM_STORE_H(0, a0x, a0y, a0z, a0w)
        MM_STORE_H(1, a1x, a1y, a1z, a1w)
        MM_STORE_H(2, a2x, a2y, a2z, a2w)
        MM_STORE_H(3, a3x, a3y, a3z, a3w)
        #undef MM_STORE_H
        __syncthreads();
    }
}

__global__ __launch_bounds__(256) void k_mm1(const float* __restrict__ W,
                                             const float* __restrict__ b) {
    mm_body_h<20>(g_agg, W, b);
}
__global__ __launch_bounds__(256) void k_mm2(const float* __restrict__ W,
                                             const float* __restrict__ b) {
    mm_body_h<64>(g_agg, W, b);
}

// ---------------- final: (mean @ W3 + b3) @ Wl + bl -> log_softmax -------------
__global__ __launch_bounds__(128) void k_final(const float* __restrict__ W3,
                                               const float* __restrict__ b3,
                                               const float* __restrict__ Wl,
                                               const float* __restrict__ bl,
                                               float* __restrict__ out) {
    int g = blockIdx.x;
    int j = threadIdx.x;
    __shared__ float sp[64];
    __shared__ float sf[128];
    int st = g_start[g], en = g_start[g + 1];
    float inv = 1.0f / fmaxf((float)(en - st), 1.0f);
    if (j < 64) sp[j] = g_psum[g * 64 + j] * inv;
    __syncthreads();
    float f = b3[j];
    #pragma unroll 8
    for (int k = 0; k < 64; k++)
        f = fmaf(sp[k], W3[k * 128 + j], f);
    sf[j] = f;
    __syncthreads();
    if (j < 32) {
        float l = -INFINITY;
        if (j < 14) {
            float acc = bl[j];
            #pragma unroll 8
            for (int k = 0; k < 128; k++)
                acc = fmaf(sf[k], Wl[k * 14 + j], acc);
            l = acc;
        }
        float m = l;
        #pragma unroll
        for (int off = 16; off; off >>= 1)
            m = fmaxf(m, __shfl_xor_sync(0xFFFFFFFFu, m, off));
        float ex = (j < 14) ? expf(l - m) : 0.f;
        float s = ex;
        #pragma unroll
        for (int off = 16; off; off >>= 1)
            s += __shfl_xor_sync(0xFFFFFFFFu, s, off);
        if (j < 14) out[g * 14 + j] = l - m - logf(s);
    }
}

// ---------------- launch ----------------
extern "C" void kernel_launch(void* const* d_in, const int* in_sizes, int n_in,
                              void* d_out, int out_size) {
    const float* x     = (const float*)d_in[0];
    const void*  ei    = d_in[1];
    const void*  batch = d_in[2];
    const float* W1 = (const float*)d_in[3];
    const float* b1 = (const float*)d_in[4];
    const float* W2 = (const float*)d_in[5];
    const float* b2 = (const float*)d_in[6];
    const float* W3 = (const float*)d_in[7];
    const float* b3 = (const float*)d_in[8];
    const float* Wl = (const float*)d_in[9];
    const float* bl = (const float*)d_in[10];
    float* out = (float*)d_out;

    const int TB = 256;
    int nblkN = (N_NODES + TB - 1) / TB;
    int nblkW = N_NODES / 8;            // exact: 100000 = 12500 * 8
    int mmGrid = 592;

    k_detect<<<1, 32>>>(ei);                                        // 1
    k_prep<<<(N_NODES * 16 + TB - 1) / TB, TB>>>(x);                // 2
    k_bound<<<nblkN, TB>>>(batch);                                  // 3
    k_deg<<<(N_EDGES / 4 + TB - 1) / TB, TB>>>(ei);                 // 4 <- profiled
    k_scan1<<<SCAN_CHUNKS, 1024>>>();                               // 5
    k_scan2<<<1, 128>>>();                                          // 6
    k_scan3<<<nblkN, TB>>>();                                       // 7
    k_fill<<<(N_EDGES / 2 + TB - 1) / TB, TB>>>(ei);                // 8

    k_agg20<<<nblkW, TB>>>(x);                                      // 9
    k_mm1<<<mmGrid, TB>>>(W1, b1);                                  // 10
    k_agg64<<<nblkW, TB>>>();                                       // 11
    k_mm2<<<mmGrid, TB>>>(W2, b2);                                  // 12
    k_agg64_pool<<<nblkW, TB>>>(batch);                             // 13
    k_final<<<N_GRAPHS, 128>>>(W3, b3, Wl, bl, out);                // 14
}